// round 1
// baseline (speedup 1.0000x reference)
#include <cuda_runtime.h>
#include <math.h>

#define NB 8
#define HH 32
#define WW 32
#define CIN 256
#define NHD 8
#define DH 8
#define LL 1024
#define COUTC 192

// scratch (static device globals; no allocation)
__device__ float g_k[NB*NHD*LL*DH];
__device__ float g_q[NB*NHD*LL*DH];
__device__ float g_v[NB*NHD*LL*DH];
__device__ float g_attn[NB*LL*64];

// ---------------------------------------------------------------------------
// K1: qkv = x @ qkv_w + qkv_b  (8192 px, 256 -> 192), split heads into scratch
// grid 512, block 192 (one thread per output channel), 16 px per block
// ---------------------------------------------------------------------------
__global__ __launch_bounds__(192) void qkv_kernel(
    const float* __restrict__ x, const float* __restrict__ w,
    const float* __restrict__ bias)
{
    __shared__ float xs[16][CIN];
    int t = threadIdx.x;
    int blk = blockIdx.x;
    const float4* xg = (const float4*)(x + (size_t)blk * 16 * CIN);
    float4* xs4 = (float4*)xs;
    for (int idx = t; idx < 16 * CIN / 4; idx += 192) xs4[idx] = xg[idx];
    __syncthreads();

    float acc[16];
    float bv = bias[t];
#pragma unroll
    for (int p = 0; p < 16; p++) acc[p] = bv;

    for (int c = 0; c < CIN; c++) {
        float wv = __ldg(&w[c * 192 + t]);
#pragma unroll
        for (int p = 0; p < 16; p++) acc[p] = fmaf(xs[p][c], wv, acc[p]);
    }

    int sect = t >> 6;          // 0=k, 1=q, 2=v
    int cc = t & 63;
    int n = cc >> 3, d = cc & 7;
    float* dst = (sect == 0) ? g_k : ((sect == 1) ? g_q : g_v);
    float scale = (sect == 1) ? 0.35355339059327379f : 1.0f;  // DKH^-0.5
#pragma unroll
    for (int p = 0; p < 16; p++) {
        int gp = blk * 16 + p;
        int b = gp >> 10, i = gp & 1023;
        dst[(((size_t)(b * NHD + n) * LL + i) << 3) + d] = acc[p] * scale;
    }
}

// ---------------------------------------------------------------------------
// K2: attention. grid 256 = (b*8+n)*4 + qchunk ; block 256 (1 thread = 1 query)
// smem: K[1024][8] V[1024][8], rel-bias tables rw/rh [64][256], rel weights
// logit(i=(x,y), j=(x2,y2)) = q.k[j] + q.Rw[y2-y+31] + q.Rh[x2-x+31]
// ---------------------------------------------------------------------------
__global__ __launch_bounds__(256) void attn_kernel(
    const float* __restrict__ krw_g, const float* __restrict__ krh_g)
{
    extern __shared__ float sm[];
    float* ksm = sm;              // 8192
    float* vsm = sm + 8192;       // 8192
    float* rw  = sm + 16384;      // 64*256
    float* rh  = sm + 32768;      // 64*256
    float* krw = sm + 49152;      // 63*8 (pad)
    float* krh = sm + 49664;      // 63*8

    int t = threadIdx.x;
    int bid = blockIdx.x;
    int qc   = bid & 3;
    int head = bid >> 2;          // b*8+n
    int n = head & 7;
    int b = head >> 3;

    const float4* kg = (const float4*)(g_k + (size_t)head * 8192);
    const float4* vg = (const float4*)(g_v + (size_t)head * 8192);
    float4* k4s = (float4*)ksm;
    float4* v4s = (float4*)vsm;
    for (int idx = t; idx < 2048; idx += 256) { k4s[idx] = kg[idx]; v4s[idx] = vg[idx]; }
    for (int idx = t; idx < 504; idx += 256) { krw[idx] = krw_g[idx]; krh[idx] = krh_g[idx]; }
    __syncthreads();

    int i = qc * 256 + t;
    int yq = i & 31;
    int xq = i >> 5;
    float4 qa = *(const float4*)(g_q + (size_t)head * 8192 + i * 8);
    float4 qb = *(const float4*)(g_q + (size_t)head * 8192 + i * 8 + 4);

    // per-thread relative-bias tables (conflict-free: [idx][t] layout)
    for (int d = 0; d < 63; d++) {
        const float* r1 = krw + d * 8;
        float s1 = fmaf(qa.x, r1[0], fmaf(qa.y, r1[1], fmaf(qa.z, r1[2], qa.w * r1[3])))
                 + fmaf(qb.x, r1[4], fmaf(qb.y, r1[5], fmaf(qb.z, r1[6], qb.w * r1[7])));
        rw[d * 256 + t] = s1;
        const float* r2 = krh + d * 8;
        float s2 = fmaf(qa.x, r2[0], fmaf(qa.y, r2[1], fmaf(qa.z, r2[2], qa.w * r2[3])))
                 + fmaf(qb.x, r2[4], fmaf(qb.y, r2[5], fmaf(qb.z, r2[6], qb.w * r2[7])));
        rh[d * 256 + t] = s2;
    }
    // no sync needed: each thread reads only its own column

    float m = -1e30f, s = 0.f;
    float a0=0,a1=0,a2=0,a3=0,a4=0,a5=0,a6=0,a7=0;
    const float* rwp = rw + (31 - yq) * 256 + t;   // rwp[y2*256]
    const float* rhp = rh + (31 - xq) * 256 + t;   // rhp[x2*256]

    for (int x2 = 0; x2 < 32; x2++) {
        float rhv = rhp[x2 * 256];
#pragma unroll 4
        for (int y2 = 0; y2 < 32; y2++) {
            int j = (x2 << 5) + y2;
            float4 ka = k4s[j * 2];
            float4 kb = k4s[j * 2 + 1];
            float l  = fmaf(qa.x, ka.x, fmaf(qa.y, ka.y, fmaf(qa.z, ka.z, qa.w * ka.w)));
            float l2 = fmaf(qb.x, kb.x, fmaf(qb.y, kb.y, fmaf(qb.z, kb.z, qb.w * kb.w)));
            l = l + l2 + rhv + rwp[y2 * 256];
            float4 va = v4s[j * 2];
            float4 vb = v4s[j * 2 + 1];
            if (l > m) {
                float c = __expf(m - l);
                s = fmaf(s, c, 1.f);
                a0 = fmaf(a0, c, va.x); a1 = fmaf(a1, c, va.y);
                a2 = fmaf(a2, c, va.z); a3 = fmaf(a3, c, va.w);
                a4 = fmaf(a4, c, vb.x); a5 = fmaf(a5, c, vb.y);
                a6 = fmaf(a6, c, vb.z); a7 = fmaf(a7, c, vb.w);
                m = l;
            } else {
                float wgt = __expf(l - m);
                s += wgt;
                a0 = fmaf(wgt, va.x, a0); a1 = fmaf(wgt, va.y, a1);
                a2 = fmaf(wgt, va.z, a2); a3 = fmaf(wgt, va.w, a3);
                a4 = fmaf(wgt, vb.x, a4); a5 = fmaf(wgt, vb.y, a5);
                a6 = fmaf(wgt, vb.z, a6); a7 = fmaf(wgt, vb.w, a7);
            }
        }
    }
    float inv = 1.f / s;
    float* op = g_attn + ((size_t)(b * LL + i)) * 64 + n * 8;
    op[0]=a0*inv; op[1]=a1*inv; op[2]=a2*inv; op[3]=a3*inv;
    op[4]=a4*inv; op[5]=a5*inv; op[6]=a6*inv; op[7]=a7*inv;
}

// ---------------------------------------------------------------------------
// K3: out-proj 64x64 + bias, write channels [192,256) of output
// ---------------------------------------------------------------------------
__global__ __launch_bounds__(64) void proj_kernel(
    const float* __restrict__ aw, const float* __restrict__ ab,
    float* __restrict__ out)
{
    __shared__ float as[16][64];
    __shared__ float ws[64][64];
    int t = threadIdx.x;   // 64
    int blk = blockIdx.x;  // 512
    {
        const float4* wg = (const float4*)aw;
        float4* wd = (float4*)ws;
        for (int idx = t; idx < 1024; idx += 64) wd[idx] = wg[idx];
        const float4* ag = (const float4*)(g_attn + (size_t)blk * 16 * 64);
        float4* as4 = (float4*)as;
        for (int idx = t; idx < 256; idx += 64) as4[idx] = ag[idx];
    }
    __syncthreads();
    float acc[16];
    float bv = ab[t];
#pragma unroll
    for (int p = 0; p < 16; p++) acc[p] = bv;
    for (int c = 0; c < 64; c++) {
        float wv = ws[c][t];
#pragma unroll
        for (int p = 0; p < 16; p++) acc[p] = fmaf(as[p][c], wv, acc[p]);
    }
    for (int p = 0; p < 16; p++) {
        int gp = blk * 16 + p;
        out[(size_t)gp * 256 + 192 + p - p + t] = acc[p];  // channel 192+t
    }
}

// ---------------------------------------------------------------------------
// K4: 3x3 conv 256->192, SAME. grid 512 = b*64 + y*2 + half (16 px per block)
// smem: input halo tile [3][18][stride 260] + double-buffered weight chunk
// thread tile: 2 px x 6 cout, K-loop over 72 chunks of (tap, 32 cin)
// ---------------------------------------------------------------------------
#define XS 260
__global__ __launch_bounds__(256) void conv_kernel(
    const float* __restrict__ x, const float* __restrict__ cw,
    const float* __restrict__ cb, float* __restrict__ out)
{
    extern __shared__ float sm[];
    float* in_t = sm;            // 3*18*260 = 14040 floats
    float* w_t  = sm + 14040;    // 2 * 6144 floats

    int t = threadIdx.x;
    int bid = blockIdx.x;
    int half = bid & 1;
    int y = (bid >> 1) & 31;
    int b = bid >> 6;
    int x0 = half << 4;

    // stage input halo tile (zeros outside the image)
    for (int idx = t; idx < 3456; idx += 256) {
        int c4 = idx & 63;
        int xx = (idx >> 6) % 18;
        int r  = idx / (64 * 18);
        int gy = y - 1 + r, gx = x0 - 1 + xx;
        float4 v = make_float4(0.f, 0.f, 0.f, 0.f);
        if ((unsigned)gy < 32u && (unsigned)gx < 32u)
            v = ((const float4*)(x + (((size_t)((b * 32 + gy) * 32 + gx)) << 8)))[c4];
        *(float4*)(in_t + (r * 18 + xx) * XS + (c4 << 2)) = v;
    }
    // stage weight chunk 0
    {
        const float4* wg0 = (const float4*)cw;
#pragma unroll
        for (int k2 = 0; k2 < 6; k2++) ((float4*)w_t)[t + k2 * 256] = wg0[t + k2 * 256];
    }
    __syncthreads();

    int pxg = t & 7;      // pixels pxg and pxg+8
    int cg  = t >> 3;     // couts 6*cg .. 6*cg+5
    int co  = cg * 6;

    float acc[2][6];
#pragma unroll
    for (int o = 0; o < 6; o++) { float bv = cb[co + o]; acc[0][o] = bv; acc[1][o] = bv; }

    for (int ck = 0; ck < 72; ck++) {
        int buf = ck & 1;
        float4 pf[6];
        if (ck < 71) {
            const float4* wg = (const float4*)(cw + (size_t)(ck + 1) * 6144);
#pragma unroll
            for (int k2 = 0; k2 < 6; k2++) pf[k2] = wg[t + k2 * 256];
        }
        int ky  = ck / 24;
        int kx  = (ck / 8) % 3;
        int cbk = ck & 7;
        const float* wt  = w_t + buf * 6144;
        const float* a0p = in_t + (ky * 18 + pxg + kx) * XS + (cbk << 5);
        const float* a1p = a0p + 8 * XS;
#pragma unroll
        for (int c = 0; c < 32; c += 4) {
            float4 A0 = *(const float4*)(a0p + c);
            float4 A1 = *(const float4*)(a1p + c);
            float a0v[4] = {A0.x, A0.y, A0.z, A0.w};
            float a1v[4] = {A1.x, A1.y, A1.z, A1.w};
#pragma unroll
            for (int u = 0; u < 4; u++) {
                const float* wr = wt + (c + u) * 192 + co;
                float av0 = a0v[u], av1 = a1v[u];
#pragma unroll
                for (int o = 0; o < 6; o++) {
                    float wv = wr[o];
                    acc[0][o] = fmaf(av0, wv, acc[0][o]);
                    acc[1][o] = fmaf(av1, wv, acc[1][o]);
                }
            }
        }
        if (ck < 71) {
            float4* wd = (float4*)(w_t + (buf ^ 1) * 6144);
#pragma unroll
            for (int k2 = 0; k2 < 6; k2++) wd[t + k2 * 256] = pf[k2];
            __syncthreads();
        }
    }

#pragma unroll
    for (int ii = 0; ii < 2; ii++) {
        int gx = x0 + pxg + (ii << 3);
        float* op = out + ((size_t)((b * 32 + y) * 32 + gx)) * 256 + co;
#pragma unroll
        for (int o = 0; o < 6; o++) op[o] = acc[ii][o];
    }
}

// ---------------------------------------------------------------------------
extern "C" void kernel_launch(void* const* d_in, const int* in_sizes, int n_in,
                              void* d_out, int out_size)
{
    const float* x      = (const float*)d_in[0];
    const float* conv_w = (const float*)d_in[1];
    const float* conv_b = (const float*)d_in[2];
    const float* qkv_w  = (const float*)d_in[3];
    const float* qkv_b  = (const float*)d_in[4];
    const float* attn_w = (const float*)d_in[5];
    const float* attn_b = (const float*)d_in[6];
    const float* krw    = (const float*)d_in[7];
    const float* krh    = (const float*)d_in[8];
    float* out = (float*)d_out;

    cudaFuncSetAttribute(attn_kernel, cudaFuncAttributeMaxDynamicSharedMemorySize, 200704);
    cudaFuncSetAttribute(conv_kernel, cudaFuncAttributeMaxDynamicSharedMemorySize, 105312);

    qkv_kernel<<<512, 192>>>(x, qkv_w, qkv_b);
    attn_kernel<<<256, 256, 200704>>>(krw, krh);
    proj_kernel<<<512, 64>>>(attn_w, attn_b, out);
    conv_kernel<<<512, 256, (14040 + 2 * 6144) * 4>>>(x, conv_w, conv_b, out);
}

// round 2
// speedup vs baseline: 1.1826x; 1.1826x over previous
#include <cuda_runtime.h>
#include <math.h>

#define NB 8
#define CIN 256
#define LL 1024

typedef unsigned long long u64;

// ---------------- f32x2 helpers (Blackwell packed fp32) ----------------
__device__ __forceinline__ u64 pack2(float x) {
    u64 r; unsigned xi = __float_as_uint(x);
    asm("mov.b64 %0, {%1, %1};" : "=l"(r) : "r"(xi));
    return r;
}
__device__ __forceinline__ u64 packab(float a, float b) {
    u64 r;
    asm("mov.b64 %0, {%1, %2};" : "=l"(r) : "r"(__float_as_uint(a)), "r"(__float_as_uint(b)));
    return r;
}
__device__ __forceinline__ void fma2(u64& d, u64 a, u64 b) {
    asm("fma.rn.f32x2 %0, %1, %2, %0;" : "+l"(d) : "l"(a), "l"(b));
}
__device__ __forceinline__ u64 mul2(u64 a, u64 b) {
    u64 d; asm("mul.rn.f32x2 %0, %1, %2;" : "=l"(d) : "l"(a), "l"(b));
    return d;
}
__device__ __forceinline__ void unpack2(u64 v, float& lo, float& hi) {
    unsigned l, h;
    asm("mov.b64 {%0, %1}, %2;" : "=r"(l), "=r"(h) : "l"(v));
    lo = __uint_as_float(l); hi = __uint_as_float(h);
}

// scratch (static device globals; no allocation)
__device__ float g_k[NB*8*LL*8];
__device__ float g_q[NB*8*LL*8];
__device__ float g_v[NB*8*LL*8];
__device__ float g_attn[NB*LL*64];

// ---------------------------------------------------------------------------
// K1: qkv = x @ qkv_w + qkv_b  (8192 px, 256 -> 192), split heads into scratch
// ---------------------------------------------------------------------------
__global__ __launch_bounds__(192) void qkv_kernel(
    const float* __restrict__ x, const float* __restrict__ w,
    const float* __restrict__ bias)
{
    __shared__ float xs[16][CIN];
    int t = threadIdx.x;
    int blk = blockIdx.x;
    const float4* xg = (const float4*)(x + (size_t)blk * 16 * CIN);
    float4* xs4 = (float4*)xs;
    for (int idx = t; idx < 16 * CIN / 4; idx += 192) xs4[idx] = xg[idx];
    __syncthreads();

    float acc[16];
    float bv = bias[t];
#pragma unroll
    for (int p = 0; p < 16; p++) acc[p] = bv;

    for (int c = 0; c < CIN; c++) {
        float wv = __ldg(&w[c * 192 + t]);
#pragma unroll
        for (int p = 0; p < 16; p++) acc[p] = fmaf(xs[p][c], wv, acc[p]);
    }

    int sect = t >> 6;          // 0=k, 1=q, 2=v
    int cc = t & 63;
    int n = cc >> 3, d = cc & 7;
    float* dst = (sect == 0) ? g_k : ((sect == 1) ? g_q : g_v);
    float scale = (sect == 1) ? 0.35355339059327379f : 1.0f;  // DKH^-0.5
#pragma unroll
    for (int p = 0; p < 16; p++) {
        int gp = blk * 16 + p;
        int b = gp >> 10, i = gp & 1023;
        dst[(((size_t)(b * 8 + n) * LL + i) << 3) + d] = acc[p] * scale;
    }
}

// ---------------------------------------------------------------------------
// K2: attention. grid 512 = head*8 + qchunk ; block 128 (1 thread = 1 query)
// single-pass softmax without max-subtraction (|logit| << 88, exp is safe),
// f32x2 packed math for QK dots and P*V accumulation.
// logit(i=(x,y), j=(x2,y2)) = q.k[j] + q.Rw[y2-y+31] + q.Rh[x2-x+31]
// rel-h bias computed on the fly per x2 (uniform per warp); rel-w per-thread
// table in smem.
// ---------------------------------------------------------------------------
__global__ __launch_bounds__(128) void attn_kernel(
    const float* __restrict__ krw_g, const float* __restrict__ krh_g)
{
    extern __shared__ float sm[];
    float* ksm = sm;              // 8192
    float* vsm = sm + 8192;       // 8192
    float* rw  = sm + 16384;      // 63*128 (pad to 8192)
    float* krw = sm + 24576;      // 512
    float* krh = sm + 25088;      // 512  -> total 25600 floats = 100 KB

    int t = threadIdx.x;
    int bid = blockIdx.x;
    int qc   = bid & 7;
    int head = bid >> 3;          // b*8+n
    int n = head & 7;
    int b = head >> 3;

    const float4* kg = (const float4*)(g_k + (size_t)head * 8192);
    const float4* vg = (const float4*)(g_v + (size_t)head * 8192);
    for (int idx = t; idx < 2048; idx += 128) {
        ((float4*)ksm)[idx] = kg[idx];
        ((float4*)vsm)[idx] = vg[idx];
    }
    for (int idx = t; idx < 504; idx += 128) { krw[idx] = krw_g[idx]; krh[idx] = krh_g[idx]; }
    __syncthreads();

    int i = qc * 128 + t;
    int yq = i & 31;
    int xq = i >> 5;
    float4 qa = *(const float4*)(g_q + (size_t)head * 8192 + i * 8);
    float4 qb = *(const float4*)(g_q + (size_t)head * 8192 + i * 8 + 4);
    u64 q01 = packab(qa.x, qa.y), q23 = packab(qa.z, qa.w);
    u64 q45 = packab(qb.x, qb.y), q67 = packab(qb.z, qb.w);

    // per-thread rel-w bias table (each thread reads only its own column)
    for (int d = 0; d < 63; d++) {
        const float* r1 = krw + d * 8;
        float s1 = fmaf(qa.x, r1[0], fmaf(qa.y, r1[1], fmaf(qa.z, r1[2], qa.w * r1[3])))
                 + fmaf(qb.x, r1[4], fmaf(qb.y, r1[5], fmaf(qb.z, r1[6], qb.w * r1[7])));
        rw[d * 128 + t] = s1;
    }

    float s = 0.f;
    u64 a0 = 0ull, a1 = 0ull, a2 = 0ull, a3 = 0ull;
    const float* rwp = rw + (31 - yq) * 128 + t;   // rwp[y2*128]
    const ulonglong2* k2p = (const ulonglong2*)ksm;
    const ulonglong2* v2p = (const ulonglong2*)vsm;

    for (int x2 = 0; x2 < 32; x2++) {
        const float* r2 = krh + (x2 - xq + 31) * 8;   // uniform per warp
        float rhv = fmaf(qa.x, r2[0], fmaf(qa.y, r2[1], fmaf(qa.z, r2[2], qa.w * r2[3])))
                  + fmaf(qb.x, r2[4], fmaf(qb.y, r2[5], fmaf(qb.z, r2[6], qb.w * r2[7])));
        int jb = x2 << 5;
#pragma unroll 8
        for (int y2 = 0; y2 < 32; y2++) {
            int j = jb + y2;
            ulonglong2 kA = k2p[2 * j];
            ulonglong2 kB = k2p[2 * j + 1];
            u64 d = mul2(q01, kA.x);
            fma2(d, q23, kA.y);
            fma2(d, q45, kB.x);
            fma2(d, q67, kB.y);
            float lo, hi; unpack2(d, lo, hi);
            float l = (lo + hi) + (rhv + rwp[y2 * 128]);
            float p = __expf(l);
            s += p;
            u64 pp = pack2(p);
            ulonglong2 vA = v2p[2 * j];
            ulonglong2 vB = v2p[2 * j + 1];
            fma2(a0, pp, vA.x); fma2(a1, pp, vA.y);
            fma2(a2, pp, vB.x); fma2(a3, pp, vB.y);
        }
    }
    float inv = 1.f / s;
    float o[8];
    unpack2(a0, o[0], o[1]); unpack2(a1, o[2], o[3]);
    unpack2(a2, o[4], o[5]); unpack2(a3, o[6], o[7]);
    float* op = g_attn + ((size_t)(b * LL + i)) * 64 + n * 8;
#pragma unroll
    for (int c = 0; c < 8; c++) op[c] = o[c] * inv;
}

// ---------------------------------------------------------------------------
// K3: out-proj 64x64 + bias, write channels [192,256) of output
// ---------------------------------------------------------------------------
__global__ __launch_bounds__(64) void proj_kernel(
    const float* __restrict__ aw, const float* __restrict__ ab,
    float* __restrict__ out)
{
    __shared__ float as[16][64];
    __shared__ float ws[64][64];
    int t = threadIdx.x;   // 64
    int blk = blockIdx.x;  // 512
    {
        const float4* wg = (const float4*)aw;
        float4* wd = (float4*)ws;
        for (int idx = t; idx < 1024; idx += 64) wd[idx] = wg[idx];
        const float4* ag = (const float4*)(g_attn + (size_t)blk * 16 * 64);
        float4* as4 = (float4*)as;
        for (int idx = t; idx < 256; idx += 64) as4[idx] = ag[idx];
    }
    __syncthreads();
    float acc[16];
    float bv = ab[t];
#pragma unroll
    for (int p = 0; p < 16; p++) acc[p] = bv;
    for (int c = 0; c < 64; c++) {
        float wv = ws[c][t];
#pragma unroll
        for (int p = 0; p < 16; p++) acc[p] = fmaf(as[p][c], wv, acc[p]);
    }
    for (int p = 0; p < 16; p++) {
        int gp = blk * 16 + p;
        out[(size_t)gp * 256 + 192 + t] = acc[p];
    }
}

// ---------------------------------------------------------------------------
// K4: 3x3 conv 256->192, SAME. grid 256 = b*32 + yp*2 + half
// block covers 2 rows x 16 cols x 192 couts; 192 threads,
// thread tile 4 px x 8 couts, accumulators as f32x2 cout-pairs (FFMA2).
// smem: input halo [4 rows][18 cols][cin stride 260] + double-buffered
// 16-cin weight chunks (144 chunks over 9 taps).
// ---------------------------------------------------------------------------
#define CS 260
__global__ __launch_bounds__(192) void conv_kernel(
    const float* __restrict__ x, const float* __restrict__ cw,
    const float* __restrict__ cb, float* __restrict__ out)
{
    extern __shared__ float sm[];
    float* in_t = sm;            // 4*18*260 = 18720 floats
    float* w_t  = sm + 18720;    // 2 * 3072 floats

    int t = threadIdx.x;
    int bid = blockIdx.x;
    int half = bid & 1;
    int yp = (bid >> 1) & 15;
    int b = bid >> 5;
    int x0 = half << 4;
    int y0 = yp << 1;

    // stage input halo tile: rows y0-1..y0+2, cols x0-1..x0+16 (zeros outside)
    for (int idx = t; idx < 4608; idx += 192) {
        int c4 = idx & 63;
        int xx = (idx >> 6) % 18;
        int r  = idx / (64 * 18);
        int gy = y0 - 1 + r, gx = x0 - 1 + xx;
        float4 v = make_float4(0.f, 0.f, 0.f, 0.f);
        if ((unsigned)gy < 32u && (unsigned)gx < 32u)
            v = ((const float4*)(x + (((size_t)((b * 32 + gy) * 32 + gx)) << 8)))[c4];
        *(float4*)(in_t + (r * 18 + xx) * CS + (c4 << 2)) = v;
    }
    // stage weight chunk 0 (16 cin x 192 couts = 768 float4)
    {
        const float4* wg = (const float4*)cw;
#pragma unroll
        for (int k2 = 0; k2 < 4; k2++)
            ((float4*)w_t)[t + k2 * 192] = wg[t + k2 * 192];
    }
    __syncthreads();

    int cg = t % 24;         // cout group: couts 8*cg .. 8*cg+7
    int pg = t / 24;         // pixel group: row r, cols cx0..cx0+3
    int r  = pg >> 2;
    int cx0 = (pg & 3) << 2;
    int co = cg << 3;

    u64 acc[4][4];
#pragma unroll
    for (int q = 0; q < 4; q++) {
        u64 bb = packab(cb[co + 2 * q], cb[co + 2 * q + 1]);
        acc[0][q] = bb; acc[1][q] = bb; acc[2][q] = bb; acc[3][q] = bb;
    }

    for (int ck = 0; ck < 144; ck++) {
        int buf = ck & 1;
        float4 pf[4];
        if (ck < 143) {
            const float4* wg = (const float4*)(cw + (size_t)(ck + 1) * 3072);
#pragma unroll
            for (int k2 = 0; k2 < 4; k2++) pf[k2] = wg[t + k2 * 192];
        }
        int tap = ck >> 4;
        int ky = tap / 3, kx = tap % 3;
        int cinb = (ck & 15) << 4;
        const float* wb = w_t + buf * 3072;
        const float* ap0 = in_t + ((r + ky) * 18 + cx0 + kx) * CS + cinb;

#pragma unroll
        for (int cc = 0; cc < 16; cc += 4) {
            float Af[16];
#pragma unroll
            for (int p = 0; p < 4; p++) {
                float4 tmp = *(const float4*)(ap0 + p * CS + cc);
                Af[p * 4 + 0] = tmp.x; Af[p * 4 + 1] = tmp.y;
                Af[p * 4 + 2] = tmp.z; Af[p * 4 + 3] = tmp.w;
            }
#pragma unroll
            for (int u = 0; u < 4; u++) {
                const ulonglong2* wr = (const ulonglong2*)(wb + (cc + u) * 192 + co);
                ulonglong2 w01 = wr[0];
                ulonglong2 w23 = wr[1];
#pragma unroll
                for (int p = 0; p < 4; p++) {
                    u64 av = pack2(Af[p * 4 + u]);
                    fma2(acc[p][0], av, w01.x);
                    fma2(acc[p][1], av, w01.y);
                    fma2(acc[p][2], av, w23.x);
                    fma2(acc[p][3], av, w23.y);
                }
            }
        }
        if (ck < 143) {
            float4* wd = (float4*)(w_t + (buf ^ 1) * 3072);
#pragma unroll
            for (int k2 = 0; k2 < 4; k2++) wd[t + k2 * 192] = pf[k2];
            __syncthreads();
        }
    }

#pragma unroll
    for (int p = 0; p < 4; p++) {
        int gx = x0 + cx0 + p;
        float* op = out + (((size_t)((b * 32 + y0 + r) * 32 + gx)) << 8) + co;
        float o[8];
        unpack2(acc[p][0], o[0], o[1]); unpack2(acc[p][1], o[2], o[3]);
        unpack2(acc[p][2], o[4], o[5]); unpack2(acc[p][3], o[6], o[7]);
        *(float4*)(op)     = make_float4(o[0], o[1], o[2], o[3]);
        *(float4*)(op + 4) = make_float4(o[4], o[5], o[6], o[7]);
    }
}

// ---------------------------------------------------------------------------
extern "C" void kernel_launch(void* const* d_in, const int* in_sizes, int n_in,
                              void* d_out, int out_size)
{
    const float* x      = (const float*)d_in[0];
    const float* conv_w = (const float*)d_in[1];
    const float* conv_b = (const float*)d_in[2];
    const float* qkv_w  = (const float*)d_in[3];
    const float* qkv_b  = (const float*)d_in[4];
    const float* attn_w = (const float*)d_in[5];
    const float* attn_b = (const float*)d_in[6];
    const float* krw    = (const float*)d_in[7];
    const float* krh    = (const float*)d_in[8];
    float* out = (float*)d_out;

    cudaFuncSetAttribute(attn_kernel, cudaFuncAttributeMaxDynamicSharedMemorySize, 102400);
    cudaFuncSetAttribute(conv_kernel, cudaFuncAttributeMaxDynamicSharedMemorySize, 99456);

    qkv_kernel<<<512, 192>>>(x, qkv_w, qkv_b);
    attn_kernel<<<512, 128, 102400>>>(krw, krh);
    proj_kernel<<<512, 64>>>(attn_w, attn_b, out);
    conv_kernel<<<256, 192, 99456>>>(x, conv_w, conv_b, out);
}

// round 6
// speedup vs baseline: 1.4226x; 1.2030x over previous
#include <cuda_runtime.h>
#include <math.h>

#define NB 8
#define CIN 256
#define LL 1024

typedef unsigned long long u64;

// ---------------- f32x2 helpers (Blackwell packed fp32) ----------------
__device__ __forceinline__ u64 pack2(float x) {
    u64 r; unsigned xi = __float_as_uint(x);
    asm("mov.b64 %0, {%1, %1};" : "=l"(r) : "r"(xi));
    return r;
}
__device__ __forceinline__ u64 packab(float a, float b) {
    u64 r;
    asm("mov.b64 %0, {%1, %2};" : "=l"(r) : "r"(__float_as_uint(a)), "r"(__float_as_uint(b)));
    return r;
}
__device__ __forceinline__ void fma2(u64& d, u64 a, u64 b) {
    asm("fma.rn.f32x2 %0, %1, %2, %0;" : "+l"(d) : "l"(a), "l"(b));
}
__device__ __forceinline__ u64 mul2(u64 a, u64 b) {
    u64 d; asm("mul.rn.f32x2 %0, %1, %2;" : "=l"(d) : "l"(a), "l"(b));
    return d;
}
__device__ __forceinline__ void unpack2(u64 v, float& lo, float& hi) {
    unsigned l, h;
    asm("mov.b64 {%0, %1}, %2;" : "=r"(l), "=r"(h) : "l"(v));
    lo = __uint_as_float(l); hi = __uint_as_float(h);
}

// scratch (static device globals; no allocation)
__device__ float g_k[NB*8*LL*8];
__device__ float g_q[NB*8*LL*8];
__device__ float g_v[NB*8*LL*8];
__device__ float g_attn[NB*LL*64];

// ---------------------------------------------------------------------------
// K1: qkv = x @ qkv_w + qkv_b  (8192 px, 256 -> 192), split heads into scratch
// ---------------------------------------------------------------------------
__global__ __launch_bounds__(192) void qkv_kernel(
    const float* __restrict__ x, const float* __restrict__ w,
    const float* __restrict__ bias)
{
    __shared__ float xs[16][CIN];
    int t = threadIdx.x;
    int blk = blockIdx.x;
    const float4* xg = (const float4*)(x + (size_t)blk * 16 * CIN);
    float4* xs4 = (float4*)xs;
    for (int idx = t; idx < 16 * CIN / 4; idx += 192) xs4[idx] = xg[idx];
    __syncthreads();

    float acc[16];
    float bv = bias[t];
#pragma unroll
    for (int p = 0; p < 16; p++) acc[p] = bv;

    for (int c = 0; c < CIN; c++) {
        float wv = __ldg(&w[c * 192 + t]);
#pragma unroll
        for (int p = 0; p < 16; p++) acc[p] = fmaf(xs[p][c], wv, acc[p]);
    }

    int sect = t >> 6;          // 0=k, 1=q, 2=v
    int cc = t & 63;
    int n = cc >> 3, d = cc & 7;
    float* dst = (sect == 0) ? g_k : ((sect == 1) ? g_q : g_v);
    float scale = (sect == 1) ? 0.35355339059327379f : 1.0f;  // DKH^-0.5
#pragma unroll
    for (int p = 0; p < 16; p++) {
        int gp = blk * 16 + p;
        int b = gp >> 10, i = gp & 1023;
        dst[(((size_t)(b * 8 + n) * LL + i) << 3) + d] = acc[p] * scale;
    }
}

// ---------------------------------------------------------------------------
// K2: attention. grid 512 = head*8 + qchunk ; block 128 (1 thread = 1 query)
// single-pass softmax without max-subtraction, f32x2 packed math.
// ---------------------------------------------------------------------------
__global__ __launch_bounds__(128) void attn_kernel(
    const float* __restrict__ krw_g, const float* __restrict__ krh_g)
{
    extern __shared__ float sm[];
    float* ksm = sm;              // 8192
    float* vsm = sm + 8192;       // 8192
    float* rw  = sm + 16384;      // 63*128 (pad to 8192)
    float* krw = sm + 24576;      // 512
    float* krh = sm + 25088;      // 512  -> total 25600 floats = 100 KB

    int t = threadIdx.x;
    int bid = blockIdx.x;
    int qc   = bid & 7;
    int head = bid >> 3;          // b*8+n
    int n = head & 7;
    int b = head >> 3;

    const float4* kg = (const float4*)(g_k + (size_t)head * 8192);
    const float4* vg = (const float4*)(g_v + (size_t)head * 8192);
    for (int idx = t; idx < 2048; idx += 128) {
        ((float4*)ksm)[idx] = kg[idx];
        ((float4*)vsm)[idx] = vg[idx];
    }
    for (int idx = t; idx < 504; idx += 128) { krw[idx] = krw_g[idx]; krh[idx] = krh_g[idx]; }
    __syncthreads();

    int i = qc * 128 + t;
    int yq = i & 31;
    int xq = i >> 5;
    float4 qa = *(const float4*)(g_q + (size_t)head * 8192 + i * 8);
    float4 qb = *(const float4*)(g_q + (size_t)head * 8192 + i * 8 + 4);
    u64 q01 = packab(qa.x, qa.y), q23 = packab(qa.z, qa.w);
    u64 q45 = packab(qb.x, qb.y), q67 = packab(qb.z, qb.w);

    for (int d = 0; d < 63; d++) {
        const float* r1 = krw + d * 8;
        float s1 = fmaf(qa.x, r1[0], fmaf(qa.y, r1[1], fmaf(qa.z, r1[2], qa.w * r1[3])))
                 + fmaf(qb.x, r1[4], fmaf(qb.y, r1[5], fmaf(qb.z, r1[6], qb.w * r1[7])));
        rw[d * 128 + t] = s1;
    }

    float s = 0.f;
    u64 a0 = 0ull, a1 = 0ull, a2 = 0ull, a3 = 0ull;
    const float* rwp = rw + (31 - yq) * 128 + t;
    const ulonglong2* k2p = (const ulonglong2*)ksm;
    const ulonglong2* v2p = (const ulonglong2*)vsm;

    for (int x2 = 0; x2 < 32; x2++) {
        const float* r2 = krh + (x2 - xq + 31) * 8;
        float rhv = fmaf(qa.x, r2[0], fmaf(qa.y, r2[1], fmaf(qa.z, r2[2], qa.w * r2[3])))
                  + fmaf(qb.x, r2[4], fmaf(qb.y, r2[5], fmaf(qb.z, r2[6], qb.w * r2[7])));
        int jb = x2 << 5;
#pragma unroll 8
        for (int y2 = 0; y2 < 32; y2++) {
            int j = jb + y2;
            ulonglong2 kA = k2p[2 * j];
            ulonglong2 kB = k2p[2 * j + 1];
            u64 d = mul2(q01, kA.x);
            fma2(d, q23, kA.y);
            fma2(d, q45, kB.x);
            fma2(d, q67, kB.y);
            float lo, hi; unpack2(d, lo, hi);
            float l = (lo + hi) + (rhv + rwp[y2 * 128]);
            float p = __expf(l);
            s += p;
            u64 pp = pack2(p);
            ulonglong2 vA = v2p[2 * j];
            ulonglong2 vB = v2p[2 * j + 1];
            fma2(a0, pp, vA.x); fma2(a1, pp, vA.y);
            fma2(a2, pp, vB.x); fma2(a3, pp, vB.y);
        }
    }
    float inv = 1.f / s;
    float o[8];
    unpack2(a0, o[0], o[1]); unpack2(a1, o[2], o[3]);
    unpack2(a2, o[4], o[5]); unpack2(a3, o[6], o[7]);
    float* op = g_attn + ((size_t)(b * LL + i)) * 64 + n * 8;
#pragma unroll
    for (int c = 0; c < 8; c++) op[c] = o[c] * inv;
}

// ---------------------------------------------------------------------------
// K3: out-proj 64x64 + bias, write channels [192,256) of output
// ---------------------------------------------------------------------------
__global__ __launch_bounds__(64) void proj_kernel(
    const float* __restrict__ aw, const float* __restrict__ ab,
    float* __restrict__ out)
{
    __shared__ float as[16][64];
    __shared__ float ws[64][64];
    int t = threadIdx.x;   // 64
    int blk = blockIdx.x;  // 512
    {
        const float4* wg = (const float4*)aw;
        float4* wd = (float4*)ws;
        for (int idx = t; idx < 1024; idx += 64) wd[idx] = wg[idx];
        const float4* ag = (const float4*)(g_attn + (size_t)blk * 16 * 64);
        float4* as4 = (float4*)as;
        for (int idx = t; idx < 256; idx += 64) as4[idx] = ag[idx];
    }
    __syncthreads();
    float acc[16];
    float bv = ab[t];
#pragma unroll
    for (int p = 0; p < 16; p++) acc[p] = bv;
    for (int c = 0; c < 64; c++) {
        float wv = ws[c][t];
#pragma unroll
        for (int p = 0; p < 16; p++) acc[p] = fmaf(as[p][c], wv, acc[p]);
    }
    for (int p = 0; p < 16; p++) {
        int gp = blk * 16 + p;
        out[(size_t)gp * 256 + 192 + t] = acc[p];
    }
}

// ---------------------------------------------------------------------------
// K4: 3x3 conv 256->192, SAME.
// grid 256 = b*32 + yp*2 + half (2 rows x 16 cols per block), 192 threads.
// Chunked double-buffered smem: input [4][18][16cin] (1152 fl) + weights
// [16cin][192] (3072 fl), both x2 buffers = 33 KB static -> 3 blocks/SM.
// Thread tile 4 px x 8 couts as two contiguous 4-cout groups (4cg, 96+4cg)
// -> conflict-free dense weight LDS.128. FFMA2 accumulators.
// 144 steps = 16 cin-chunks x 9 taps.
// ---------------------------------------------------------------------------
__global__ __launch_bounds__(192, 3) void conv_kernel(
    const float* __restrict__ x, const float* __restrict__ cw,
    const float* __restrict__ cb, float* __restrict__ out)
{
    __shared__ __align__(16) float in_t[2][1152];   // [4 rows][18 cols][16 cin]
    __shared__ __align__(16) float w_t[2][3072];    // [16 cin][192 cout]

    int t = threadIdx.x;
    int bid = blockIdx.x;
    int half = bid & 1;
    int yp = (bid >> 1) & 15;
    int b = bid >> 5;
    int x0 = half << 4;
    int y0 = yp << 1;

    int cg  = t % 24;
    int pg  = t / 24;            // 0..7
    int r   = pg >> 2;           // 0..1
    int cx0 = (pg & 3) << 2;     // 0,4,8,12
    int colo = cg << 2;          // 0..92
    int cohi = 96 + colo;        // 96..188

    // ---- initial stage: input chunk 0 + weight chunk (tap0, cin 0..15) ----
    {
        // input: 288 float4 (4 rows x 18 cols x 4 f4)
        for (int idx = t; idx < 288; idx += 192) {
            int f4  = idx & 3;
            int col = (idx >> 2) % 18;
            int row = (idx >> 2) / 18;
            int gy = y0 - 1 + row, gx = x0 - 1 + col;
            float4 v = make_float4(0.f, 0.f, 0.f, 0.f);
            if ((unsigned)gy < 32u && (unsigned)gx < 32u)
                v = *(const float4*)(x + (((size_t)((b * 32 + gy) * 32 + gx)) << 8) + f4 * 4);
            *(float4*)(&in_t[0][(row * 18 + col) * 16 + f4 * 4]) = v;
        }
        const float4* wg = (const float4*)cw;
#pragma unroll
        for (int k2 = 0; k2 < 4; k2++)
            ((float4*)w_t[0])[t + k2 * 192] = wg[t + k2 * 192];
    }
    __syncthreads();

    u64 acc[4][4];
#pragma unroll
    for (int p = 0; p < 4; p++) {
        acc[p][0] = packab(cb[colo],     cb[colo + 1]);
        acc[p][1] = packab(cb[colo + 2], cb[colo + 3]);
        acc[p][2] = packab(cb[cohi],     cb[cohi + 1]);
        acc[p][3] = packab(cb[cohi + 2], cb[cohi + 3]);
    }

    for (int s = 0; s < 144; s++) {
        int wbuf = s & 1;
        int c16  = s / 9;
        int tap  = s - c16 * 9;
        int ibuf = c16 & 1;

        // prefetch next weight chunk to regs
        float4 wpre[4];
        if (s < 143) {
            int ns = s + 1;
            int nc = ns / 9;
            int nt = ns - nc * 9;
            const float4* wg = (const float4*)(cw + ((size_t)nt * 256 + nc * 16) * 192);
#pragma unroll
            for (int k2 = 0; k2 < 4; k2++) wpre[k2] = wg[t + k2 * 192];
        }
        // prefetch next input chunk (only on last tap of a chunk)
        float4 ipre0, ipre1;
        bool ipref = (tap == 8) && (c16 < 15);
        if (ipref) {
            int cinb = (c16 + 1) * 16;
            {
                int idx = t;
                int f4  = idx & 3;
                int col = (idx >> 2) % 18;
                int row = (idx >> 2) / 18;
                int gy = y0 - 1 + row, gx = x0 - 1 + col;
                ipre0 = make_float4(0.f, 0.f, 0.f, 0.f);
                if ((unsigned)gy < 32u && (unsigned)gx < 32u)
                    ipre0 = *(const float4*)(x + (((size_t)((b * 32 + gy) * 32 + gx)) << 8) + cinb + f4 * 4);
            }
            if (t < 96) {
                int idx = t + 192;
                int f4  = idx & 3;
                int col = (idx >> 2) % 18;
                int row = (idx >> 2) / 18;
                int gy = y0 - 1 + row, gx = x0 - 1 + col;
                ipre1 = make_float4(0.f, 0.f, 0.f, 0.f);
                if ((unsigned)gy < 32u && (unsigned)gx < 32u)
                    ipre1 = *(const float4*)(x + (((size_t)((b * 32 + gy) * 32 + gx)) << 8) + cinb + f4 * 4);
            }
        }

        // ---- compute this (chunk, tap) ----
        int ky = tap / 3, kx = tap - ky * 3;
        const float* ap = &in_t[ibuf][((r + ky) * 18 + cx0 + kx) * 16];
        const float* wp = w_t[wbuf];
#pragma unroll
        for (int cc = 0; cc < 16; cc += 4) {
            float4 A0 = *(const float4*)(ap + 0 * 16 + cc);
            float4 A1 = *(const float4*)(ap + 1 * 16 + cc);
            float4 A2 = *(const float4*)(ap + 2 * 16 + cc);
            float4 A3 = *(const float4*)(ap + 3 * 16 + cc);
            float Af[4][4] = {
                {A0.x, A0.y, A0.z, A0.w},
                {A1.x, A1.y, A1.z, A1.w},
                {A2.x, A2.y, A2.z, A2.w},
                {A3.x, A3.y, A3.z, A3.w}};
#pragma unroll
            for (int u = 0; u < 4; u++) {
                const float* wr = wp + (cc + u) * 192;
                ulonglong2 wl = *(const ulonglong2*)(wr + colo);
                ulonglong2 wh = *(const ulonglong2*)(wr + cohi);
#pragma unroll
                for (int p = 0; p < 4; p++) {
                    u64 av = pack2(Af[p][u]);
                    fma2(acc[p][0], av, wl.x);
                    fma2(acc[p][1], av, wl.y);
                    fma2(acc[p][2], av, wh.x);
                    fma2(acc[p][3], av, wh.y);
                }
            }
        }

        // ---- store prefetched data to the other buffers ----
        if (s < 143) {
            float4* wd = (float4*)w_t[wbuf ^ 1];
#pragma unroll
            for (int k2 = 0; k2 < 4; k2++) wd[t + k2 * 192] = wpre[k2];
            if (ipref) {
                float* dst = in_t[ibuf ^ 1];
                {
                    int idx = t;
                    int f4 = idx & 3, col = (idx >> 2) % 18, row = (idx >> 2) / 18;
                    *(float4*)(&dst[(row * 18 + col) * 16 + f4 * 4]) = ipre0;
                }
                if (t < 96) {
                    int idx = t + 192;
                    int f4 = idx & 3, col = (idx >> 2) % 18, row = (idx >> 2) / 18;
                    *(float4*)(&dst[(row * 18 + col) * 16 + f4 * 4]) = ipre1;
                }
            }
            __syncthreads();
        }
    }

    // ---- epilogue ----
#pragma unroll
    for (int p = 0; p < 4; p++) {
        int gx = x0 + cx0 + p;
        float* op = out + (((size_t)((b * 32 + y0 + r) * 32 + gx)) << 8);
        float o0, o1, o2, o3;
        unpack2(acc[p][0], o0, o1); unpack2(acc[p][1], o2, o3);
        *(float4*)(op + colo) = make_float4(o0, o1, o2, o3);
        unpack2(acc[p][2], o0, o1); unpack2(acc[p][3], o2, o3);
        *(float4*)(op + cohi) = make_float4(o0, o1, o2, o3);
    }
}

// ---------------------------------------------------------------------------
extern "C" void kernel_launch(void* const* d_in, const int* in_sizes, int n_in,
                              void* d_out, int out_size)
{
    const float* x      = (const float*)d_in[0];
    const float* conv_w = (const float*)d_in[1];
    const float* conv_b = (const float*)d_in[2];
    const float* qkv_w  = (const float*)d_in[3];
    const float* qkv_b  = (const float*)d_in[4];
    const float* attn_w = (const float*)d_in[5];
    const float* attn_b = (const float*)d_in[6];
    const float* krw    = (const float*)d_in[7];
    const float* krh    = (const float*)d_in[8];
    float* out = (float*)d_out;

    cudaFuncSetAttribute(attn_kernel, cudaFuncAttributeMaxDynamicSharedMemorySize, 102400);

    qkv_kernel<<<512, 192>>>(x, qkv_w, qkv_b);
    attn_kernel<<<512, 128, 102400>>>(krw, krh);
    proj_kernel<<<512, 64>>>(attn_w, attn_b, out);
    conv_kernel<<<256, 192>>>(x, conv_w, conv_b, out);
}